// round 7
// baseline (speedup 1.0000x reference)
#include <cuda_runtime.h>
#include <math.h>
#include <stdint.h>

#define SEQ    4096
#define DIM    1024
#define NH     16
#define HD     64
#define HIDDEN 4096

// ---------------- scratch -----------------------------------------------------------
__device__ float g_xn[SEQ * DIM];
__device__ float g_q [SEQ * DIM];
__device__ float g_k [SEQ * DIM];
__device__ float g_v [SEQ * DIM];
__device__ float g_at[SEQ * DIM];
__device__ float g_hn[SEQ * DIM];
__device__ float g_t1[SEQ * HIDDEN];
__device__ float g_t3[SEQ * HIDDEN];
__device__ float g_cos[SEQ * (HD / 2)];
__device__ float g_sin[SEQ * (HD / 2)];
__device__ float g_wt[16777216];          // tf32-rounded weights (64MB)

#define WQO 0
#define WKO 1048576
#define WVO 2097152
#define WOO 3145728
#define W1O 4194304
#define W3O 8388608
#define W2O 12582912

__device__ __forceinline__ uint32_t f2tf32(float f) {
    uint32_t u;
    asm("cvt.rna.tf32.f32 %0, %1;" : "=r"(u) : "f"(f));
    return u;
}
__device__ __forceinline__ float rtf32(float f) { return __uint_as_float(f2tf32(f)); }

__device__ __forceinline__ void mma_tf32(float* c, const uint32_t* a, uint32_t b0, uint32_t b1) {
    asm volatile(
        "mma.sync.aligned.m16n8k8.row.col.f32.tf32.tf32.f32 "
        "{%0,%1,%2,%3}, {%4,%5,%6,%7}, {%8,%9}, {%0,%1,%2,%3};\n"
        : "+f"(c[0]), "+f"(c[1]), "+f"(c[2]), "+f"(c[3])
        : "r"(a[0]), "r"(a[1]), "r"(a[2]), "r"(a[3]), "r"(b0), "r"(b1));
}

__device__ __forceinline__ void cp16(uint32_t saddr, const void* gptr) {
    asm volatile("cp.async.cg.shared.global [%0], [%1], 16;" :: "r"(saddr), "l"(gptr));
}

__device__ __forceinline__ uint32_t smem_u32(const void* p) {
    uint32_t a;
    asm("{ .reg .u64 t; cvta.to.shared.u64 t, %1; cvt.u32.u64 %0, t; }" : "=r"(a) : "l"(p));
    return a;
}

// ---------------- weight tf32 pre-round ----------------------------------------------
__global__ void cvt_w_k(const float* __restrict__ src, float* __restrict__ dst, int n4) {
    int stride = gridDim.x * blockDim.x;
    for (int i = blockIdx.x * blockDim.x + threadIdx.x; i < n4; i += stride) {
        float4 v = ((const float4*)src)[i];
        v.x = rtf32(v.x); v.y = rtf32(v.y); v.z = rtf32(v.z); v.w = rtf32(v.w);
        ((float4*)dst)[i] = v;
    }
}

// ---------------- RoPE tables in double precision ------------------------------------
__global__ void rope_tables_k(float* __restrict__ c, float* __restrict__ s) {
    int idx = blockIdx.x * blockDim.x + threadIdx.x;
    int pos = idx >> 5;
    int i   = idx & 31;
    double inv = exp(-((double)(2 * i) / (double)HD) * log(10000.0));
    double ang = (double)pos * inv;
    double cs, sn;
    sincos(ang, &sn, &cs);
    c[idx] = (float)cs;
    s[idx] = (float)sn;
}

// ---------------- RMSNorm (tf32-rounded output) ---------------------------------------
__global__ void rmsnorm_k(const float* __restrict__ x, const float* __restrict__ g,
                          float* __restrict__ o) {
    int row = blockIdx.x;
    const float4* xr = (const float4*)(x + (size_t)row * DIM);
    float4*       orow = (float4*)(o + (size_t)row * DIM);
    int t = threadIdx.x;
    float4 v = xr[t];
    float ss = v.x * v.x + v.y * v.y + v.z * v.z + v.w * v.w;
    #pragma unroll
    for (int off = 16; off; off >>= 1) ss += __shfl_xor_sync(0xffffffffu, ss, off);
    __shared__ float sp[8];
    if ((t & 31) == 0) sp[t >> 5] = ss;
    __syncthreads();
    if (t < 8) {
        float s2 = sp[t];
        #pragma unroll
        for (int off = 4; off; off >>= 1) s2 += __shfl_xor_sync(0xffu, s2, off);
        if (t == 0) sp[0] = s2;
    }
    __syncthreads();
    float rs = rsqrtf(sp[0] * (1.0f / DIM) + 1e-6f);
    float4 gg = ((const float4*)g)[t];
    float4 out;
    out.x = rtf32(v.x * rs * gg.x);
    out.y = rtf32(v.y * rs * gg.y);
    out.z = rtf32(v.z * rs * gg.z);
    out.w = rtf32(v.w * rs * gg.w);
    orow[t] = out;
}

// ---------------- tf32 GEMM: CTA 128x256, warp 64x64, cp.async 3-stage ---------------
// C[M,N] = A[M,K] @ B[N,K]^T (+res). Inputs already tf32-rounded fp32 bits.
#define BK 16
#define SST 20
#define STAGES 3
#define AW  (128 * SST)             // A stage words
#define BW  (256 * SST)             // B stage words
#define STGW (AW + BW)              // stage words
#define GSMEM (STAGES * STGW * 4)   // bytes

struct Batch3 {
    const float* B[3];
    float*       C[3];
    const float* R[3];
};

template <bool RESID>
__global__ __launch_bounds__(256, 1)
void gemm_tc(const float* __restrict__ A, Batch3 bt, int M, int N, int K) {
    extern __shared__ uint32_t sm[];
    const float* __restrict__ Bp = bt.B[blockIdx.z];
    float*       __restrict__ Cp = bt.C[blockIdx.z];
    const float* __restrict__ Rp = bt.R[blockIdx.z];

    const int bm = blockIdx.y * 128;
    const int bn = blockIdx.x * 256;
    const int tid  = threadIdx.x;
    const int warp = tid >> 5;
    const int lane = tid & 31;
    const int grp  = lane >> 2;
    const int tig  = lane & 3;
    const int wm = (warp >> 2) * 64;   // 0,64
    const int wn = (warp & 3) * 64;    // 0,64,128,192

    const int lr = tid >> 2;           // 0..63
    const int c4 = (tid & 3) * 4;

    float acc[4][8][4];
    #pragma unroll
    for (int i = 0; i < 4; i++)
        #pragma unroll
        for (int j = 0; j < 8; j++)
            #pragma unroll
            for (int r = 0; r < 4; r++) acc[i][j][r] = 0.0f;

    const int NT = K / BK;

    auto issue = [&](int kt) {
        const int st = kt % STAGES;
        uint32_t ab = smem_u32(sm) + st * STGW * 4;
        uint32_t bb = ab + AW * 4;
        const float* Ag = A  + (size_t)bm * K + kt * BK;
        const float* Bg = Bp + (size_t)bn * K + kt * BK;
        // A: 128 rows x 4 float4  (512 slots, 2 per thread)
        cp16(ab + (lr * SST + c4) * 4,        Ag + (size_t)lr * K + c4);
        cp16(ab + ((lr + 64) * SST + c4) * 4, Ag + (size_t)(lr + 64) * K + c4);
        // B: 256 rows x 4 float4  (1024 slots, 4 per thread)
        #pragma unroll
        for (int i = 0; i < 4; i++) {
            int row = lr + i * 64;
            cp16(bb + (row * SST + c4) * 4, Bg + (size_t)row * K + c4);
        }
        asm volatile("cp.async.commit_group;");
    };

    issue(0);
    issue(1);

    for (int kt = 0; kt < NT; kt++) {
        if (kt + 1 < NT) {
            asm volatile("cp.async.wait_group 1;");
        } else {
            asm volatile("cp.async.wait_group 0;");
        }
        __syncthreads();
        if (kt + 2 < NT) issue(kt + 2);

        const uint32_t* As = sm + (kt % STAGES) * STGW;
        const uint32_t* Bs = As + AW;

        #pragma unroll
        for (int ks = 0; ks < 2; ks++) {
            const int kb = ks * 8;
            uint32_t af[4][4], bf[8][2];
            #pragma unroll
            for (int mt = 0; mt < 4; mt++) {
                const int mr = wm + mt * 16;
                af[mt][0] = As[(mr + grp    ) * SST + kb + tig];
                af[mt][1] = As[(mr + grp + 8) * SST + kb + tig];
                af[mt][2] = As[(mr + grp    ) * SST + kb + tig + 4];
                af[mt][3] = As[(mr + grp + 8) * SST + kb + tig + 4];
            }
            #pragma unroll
            for (int nt = 0; nt < 8; nt++) {
                const int nr = wn + nt * 8 + grp;
                bf[nt][0] = Bs[nr * SST + kb + tig];
                bf[nt][1] = Bs[nr * SST + kb + tig + 4];
            }
            #pragma unroll
            for (int mt = 0; mt < 4; mt++)
                #pragma unroll
                for (int nt = 0; nt < 8; nt++)
                    mma_tf32(acc[mt][nt], af[mt], bf[nt][0], bf[nt][1]);
        }
    }

    #pragma unroll
    for (int mt = 0; mt < 4; mt++) {
        const int row = bm + wm + mt * 16 + grp;
        #pragma unroll
        for (int nt = 0; nt < 8; nt++) {
            const int col = bn + wn + nt * 8 + 2 * tig;
            size_t i0 = (size_t)row * N + col;
            size_t i1 = (size_t)(row + 8) * N + col;
            float2 v0 = make_float2(acc[mt][nt][0], acc[mt][nt][1]);
            float2 v1 = make_float2(acc[mt][nt][2], acc[mt][nt][3]);
            if (RESID) {
                float2 r0v = *(const float2*)&Rp[i0];
                float2 r1v = *(const float2*)&Rp[i1];
                v0.x += r0v.x; v0.y += r0v.y;
                v1.x += r1v.x; v1.y += r1v.y;
            }
            *(float2*)&Cp[i0] = v0;
            *(float2*)&Cp[i1] = v1;
        }
    }
}

// ---------------- RoPE ---------------------------------------------------------------
__global__ void rope_k(float* __restrict__ q, float* __restrict__ k,
                       const float* __restrict__ ct, const float* __restrict__ st) {
    int pos = blockIdx.x;
    int t = threadIdx.x;
    int h = t >> 5;
    int i = t & 31;
    float c = ct[pos * 32 + i];
    float s = st[pos * 32 + i];
    size_t base = (size_t)pos * DIM + h * HD + 2 * i;
    float2 qq = *(float2*)&q[base];
    float2 qo; qo.x = qq.x * c - qq.y * s; qo.y = qq.x * s + qq.y * c;
    *(float2*)&q[base] = qo;
    float2 kk = *(float2*)&k[base];
    float2 ko; ko.x = kk.x * c - kk.y * s; ko.y = kk.x * s + kk.y * c;
    *(float2*)&k[base] = ko;
}

// ---------------- Tensor-core flash attention (tf32, mma.sync) -----------------------
#define BQ   64
#define BKV  64
#define KP   68
#define VP   72

__global__ __launch_bounds__(128, 3)
void flash_attn_tc(const float* __restrict__ Q, const float* __restrict__ K,
                   const float* __restrict__ V, float* __restrict__ O) {
    __shared__ uint32_t Ks[BKV][KP];
    __shared__ uint32_t Vs[BKV][VP];
    __shared__ uint32_t Ps[BQ][KP];

    const int h  = blockIdx.y;
    const int q0 = blockIdx.x * BQ;
    const int tid  = threadIdx.x;
    const int warp = tid >> 5;
    const int lane = tid & 31;
    const int grp  = lane >> 2;
    const int tig  = lane & 3;
    const int wm   = warp * 16;

    uint32_t qf[8][4];
    {
        const float* qb = Q + (size_t)(q0 + wm) * DIM + h * HD;
        #pragma unroll
        for (int ks = 0; ks < 8; ks++) {
            qf[ks][0] = f2tf32(0.125f * qb[(size_t)grp       * DIM + ks * 8 + tig]);
            qf[ks][1] = f2tf32(0.125f * qb[(size_t)(grp + 8) * DIM + ks * 8 + tig]);
            qf[ks][2] = f2tf32(0.125f * qb[(size_t)grp       * DIM + ks * 8 + tig + 4]);
            qf[ks][3] = f2tf32(0.125f * qb[(size_t)(grp + 8) * DIM + ks * 8 + tig + 4]);
        }
    }

    float o[8][4];
    #pragma unroll
    for (int dt = 0; dt < 8; dt++)
        #pragma unroll
        for (int r = 0; r < 4; r++) o[dt][r] = 0.0f;
    float m0 = -1e30f, m1 = -1e30f, l0 = 0.0f, l1 = 0.0f;

    for (int k0 = 0; k0 < SEQ; k0 += BKV) {
        __syncthreads();
        #pragma unroll
        for (int i = 0; i < 8; i++) {
            int idx = tid + i * 128;
            int row = idx >> 4;
            int c   = (idx & 15) * 4;
            float4 k4 = *(const float4*)&K[(size_t)(k0 + row) * DIM + h * HD + c];
            Ks[row][c + 0] = f2tf32(k4.x); Ks[row][c + 1] = f2tf32(k4.y);
            Ks[row][c + 2] = f2tf32(k4.z); Ks[row][c + 3] = f2tf32(k4.w);
            float4 v4 = *(const float4*)&V[(size_t)(k0 + row) * DIM + h * HD + c];
            Vs[row][c + 0] = f2tf32(v4.x); Vs[row][c + 1] = f2tf32(v4.y);
            Vs[row][c + 2] = f2tf32(v4.z); Vs[row][c + 3] = f2tf32(v4.w);
        }
        __syncthreads();

        float sc[8][4];
        #pragma unroll
        for (int nt = 0; nt < 8; nt++)
            #pragma unroll
            for (int r = 0; r < 4; r++) sc[nt][r] = 0.0f;
        #pragma unroll
        for (int ks = 0; ks < 8; ks++) {
            const int kb = ks * 8;
            #pragma unroll
            for (int nt = 0; nt < 8; nt++) {
                uint32_t b0 = Ks[nt * 8 + grp][kb + tig];
                uint32_t b1 = Ks[nt * 8 + grp][kb + tig + 4];
                mma_tf32(sc[nt], qf[ks], b0, b1);
            }
        }

        float mx0 = -1e30f, mx1 = -1e30f;
        #pragma unroll
        for (int nt = 0; nt < 8; nt++) {
            mx0 = fmaxf(mx0, fmaxf(sc[nt][0], sc[nt][1]));
            mx1 = fmaxf(mx1, fmaxf(sc[nt][2], sc[nt][3]));
        }
        mx0 = fmaxf(mx0, __shfl_xor_sync(0xffffffffu, mx0, 1));
        mx0 = fmaxf(mx0, __shfl_xor_sync(0xffffffffu, mx0, 2));
        mx1 = fmaxf(mx1, __shfl_xor_sync(0xffffffffu, mx1, 1));
        mx1 = fmaxf(mx1, __shfl_xor_sync(0xffffffffu, mx1, 2));

        float mn0 = fmaxf(m0, mx0);
        float mn1 = fmaxf(m1, mx1);
        float cr0 = __expf(m0 - mn0);
        float cr1 = __expf(m1 - mn1);
        m0 = mn0; m1 = mn1;

        float s0 = 0.0f, s1 = 0.0f;
        #pragma unroll
        for (int nt = 0; nt < 8; nt++) {
            sc[nt][0] = __expf(sc[nt][0] - mn0);
            sc[nt][1] = __expf(sc[nt][1] - mn0);
            sc[nt][2] = __expf(sc[nt][2] - mn1);
            sc[nt][3] = __expf(sc[nt][3] - mn1);
            s0 += sc[nt][0] + sc[nt][1];
            s1 += sc[nt][2] + sc[nt][3];
        }
        s0 += __shfl_xor_sync(0xffffffffu, s0, 1);
        s0 += __shfl_xor_sync(0xffffffffu, s0, 2);
        s1 += __shfl_xor_sync(0xffffffffu, s1, 1);
        s1 += __shfl_xor_sync(0xffffffffu, s1, 2);
        l0 = l0 * cr0 + s0;
        l1 = l1 * cr1 + s1;

        #pragma unroll
        for (int dt = 0; dt < 8; dt++) {
            o[dt][0] *= cr0; o[dt][1] *= cr0;
            o[dt][2] *= cr1; o[dt][3] *= cr1;
        }

        #pragma unroll
        for (int nt = 0; nt < 8; nt++) {
            uint2 u0 = make_uint2(f2tf32(sc[nt][0]), f2tf32(sc[nt][1]));
            uint2 u1 = make_uint2(f2tf32(sc[nt][2]), f2tf32(sc[nt][3]));
            *(uint2*)&Ps[wm + grp    ][nt * 8 + 2 * tig] = u0;
            *(uint2*)&Ps[wm + grp + 8][nt * 8 + 2 * tig] = u1;
        }
        __syncwarp();

        #pragma unroll
        for (int ks = 0; ks < 8; ks++) {
            const int kb = ks * 8;
            uint32_t pa[4];
            pa[0] = Ps[wm + grp    ][kb + tig];
            pa[1] = Ps[wm + grp + 8][kb + tig];
            pa[2] = Ps[wm + grp    ][kb + tig + 4];
            pa[3] = Ps[wm + grp + 8][kb + tig + 4];
            #pragma unroll
            for (int dt = 0; dt < 8; dt++) {
                uint32_t b0 = Vs[kb + tig    ][dt * 8 + grp];
                uint32_t b1 = Vs[kb + tig + 4][dt * 8 + grp];
                mma_tf32(o[dt], pa, b0, b1);
            }
        }
        __syncwarp();
    }

    float il0 = 1.0f / l0;
    float il1 = 1.0f / l1;
    #pragma unroll
    for (int dt = 0; dt < 8; dt++) {
        size_t i0 = (size_t)(q0 + wm + grp    ) * DIM + h * HD + dt * 8 + 2 * tig;
        size_t i1 = (size_t)(q0 + wm + grp + 8) * DIM + h * HD + dt * 8 + 2 * tig;
        *(float2*)&O[i0] = make_float2(rtf32(o[dt][0] * il0), rtf32(o[dt][1] * il0));
        *(float2*)&O[i1] = make_float2(rtf32(o[dt][2] * il1), rtf32(o[dt][3] * il1));
    }
}

// ---------------- SwiGLU elementwise (tf32-rounded output) ---------------------------
__global__ void silu_mul_k(float* __restrict__ a, const float* __restrict__ b, int n4) {
    int i = blockIdx.x * blockDim.x + threadIdx.x;
    if (i < n4) {
        float4 x = ((float4*)a)[i];
        float4 y = ((const float4*)b)[i];
        x.x = rtf32(x.x / (1.0f + __expf(-x.x)) * y.x);
        x.y = rtf32(x.y / (1.0f + __expf(-x.y)) * y.y);
        x.z = rtf32(x.z / (1.0f + __expf(-x.z)) * y.z);
        x.w = rtf32(x.w / (1.0f + __expf(-x.w)) * y.w);
        ((float4*)a)[i] = x;
    }
}

// ---------------- launch --------------------------------------------------------------
extern "C" void kernel_launch(void* const* d_in, const int* in_sizes, int n_in,
                              void* d_out, int out_size) {
    const float* x  = (const float*)d_in[0];
    const float* wq = (const float*)d_in[1];
    const float* wk = (const float*)d_in[2];
    const float* wv = (const float*)d_in[3];
    const float* wo = (const float*)d_in[4];
    const float* w1 = (const float*)d_in[5];
    const float* w2 = (const float*)d_in[6];
    const float* w3 = (const float*)d_in[7];
    const float* ga = (const float*)d_in[8];
    const float* gf = (const float*)d_in[9];
    float* out = (float*)d_out;

    float *xn, *q, *k, *v, *at, *hn, *t1, *t3, *ct, *st, *wt;
    cudaGetSymbolAddress((void**)&xn, g_xn);
    cudaGetSymbolAddress((void**)&q,  g_q);
    cudaGetSymbolAddress((void**)&k,  g_k);
    cudaGetSymbolAddress((void**)&v,  g_v);
    cudaGetSymbolAddress((void**)&at, g_at);
    cudaGetSymbolAddress((void**)&hn, g_hn);
    cudaGetSymbolAddress((void**)&t1, g_t1);
    cudaGetSymbolAddress((void**)&t3, g_t3);
    cudaGetSymbolAddress((void**)&ct, g_cos);
    cudaGetSymbolAddress((void**)&st, g_sin);
    cudaGetSymbolAddress((void**)&wt, g_wt);

    cudaFuncSetAttribute(gemm_tc<false>, cudaFuncAttributeMaxDynamicSharedMemorySize, GSMEM);
    cudaFuncSetAttribute(gemm_tc<true>,  cudaFuncAttributeMaxDynamicSharedMemorySize, GSMEM);

    cvt_w_k<<<256, 256>>>(wq, wt + WQO, DIM * DIM / 4);
    cvt_w_k<<<256, 256>>>(wk, wt + WKO, DIM * DIM / 4);
    cvt_w_k<<<256, 256>>>(wv, wt + WVO, DIM * DIM / 4);
    cvt_w_k<<<256, 256>>>(wo, wt + WOO, DIM * DIM / 4);
    cvt_w_k<<<512, 256>>>(w1, wt + W1O, HIDDEN * DIM / 4);
    cvt_w_k<<<512, 256>>>(w3, wt + W3O, HIDDEN * DIM / 4);
    cvt_w_k<<<512, 256>>>(w2, wt + W2O, DIM * HIDDEN / 4);

    rope_tables_k<<<(SEQ * 32) / 256, 256>>>(ct, st);
    rmsnorm_k<<<SEQ, 256>>>(x, ga, xn);

    // QKV batched (z = 3)
    {
        Batch3 bt;
        bt.B[0] = wt + WQO; bt.B[1] = wt + WKO; bt.B[2] = wt + WVO;
        bt.C[0] = q; bt.C[1] = k; bt.C[2] = v;
        bt.R[0] = bt.R[1] = bt.R[2] = nullptr;
        gemm_tc<false><<<dim3(DIM / 256, SEQ / 128, 3), 256, GSMEM>>>(xn, bt, SEQ, DIM, DIM);
    }

    rope_k<<<SEQ, 512>>>(q, k, ct, st);
    flash_attn_tc<<<dim3(SEQ / BQ, NH), 128>>>(q, k, v, at);

    // Wo + residual -> out
    {
        Batch3 bt;
        bt.B[0] = wt + WOO; bt.C[0] = out; bt.R[0] = x;
        bt.B[1] = bt.B[2] = nullptr; bt.C[1] = bt.C[2] = nullptr; bt.R[1] = bt.R[2] = nullptr;
        gemm_tc<true><<<dim3(DIM / 256, SEQ / 128, 1), 256, GSMEM>>>(at, bt, SEQ, DIM, DIM);
    }

    rmsnorm_k<<<SEQ, 256>>>(out, gf, hn);

    // w1 / w3 batched (z = 2)
    {
        Batch3 bt;
        bt.B[0] = wt + W1O; bt.B[1] = wt + W3O; bt.B[2] = nullptr;
        bt.C[0] = t1; bt.C[1] = t3; bt.C[2] = nullptr;
        bt.R[0] = bt.R[1] = bt.R[2] = nullptr;
        gemm_tc<false><<<dim3(HIDDEN / 256, SEQ / 128, 2), 256, GSMEM>>>(hn, bt, SEQ, HIDDEN, DIM);
    }

    silu_mul_k<<<(SEQ * HIDDEN / 4 + 255) / 256, 256>>>(t1, t3, SEQ * HIDDEN / 4);

    // W2 + residual -> out
    {
        Batch3 bt;
        bt.B[0] = wt + W2O; bt.C[0] = out; bt.R[0] = out;
        bt.B[1] = bt.B[2] = nullptr; bt.C[1] = bt.C[2] = nullptr; bt.R[1] = bt.R[2] = nullptr;
        gemm_tc<true><<<dim3(DIM / 256, SEQ / 128, 1), 256, GSMEM>>>(t1, bt, SEQ, DIM, HIDDEN);
    }
}

// round 8
// speedup vs baseline: 1.1371x; 1.1371x over previous
#include <cuda_runtime.h>
#include <math.h>
#include <stdint.h>

#define SEQ    4096
#define DIM    1024
#define NH     16
#define HD     64
#define HIDDEN 4096

// ---------------- scratch -----------------------------------------------------------
__device__ float g_xn[SEQ * DIM];
__device__ float g_q [SEQ * DIM];
__device__ float g_k [SEQ * DIM];
__device__ float g_v [SEQ * DIM];
__device__ float g_at[SEQ * DIM];
__device__ float g_hn[SEQ * DIM];
__device__ float g_t1[SEQ * HIDDEN];
__device__ float g_t3[SEQ * HIDDEN];
__device__ float g_cos[SEQ * (HD / 2)];
__device__ float g_sin[SEQ * (HD / 2)];
__device__ float g_wt[16777216];          // tf32-rounded weights (64MB)

#define WQO 0
#define WKO 1048576
#define WVO 2097152
#define WOO 3145728
#define W1O 4194304
#define W3O 8388608
#define W2O 12582912

__device__ __forceinline__ uint32_t f2tf32(float f) {
    uint32_t u;
    asm("cvt.rna.tf32.f32 %0, %1;" : "=r"(u) : "f"(f));
    return u;
}
__device__ __forceinline__ float rtf32(float f) { return __uint_as_float(f2tf32(f)); }

__device__ __forceinline__ void mma_tf32(float* c, const uint32_t* a, uint32_t b0, uint32_t b1) {
    asm volatile(
        "mma.sync.aligned.m16n8k8.row.col.f32.tf32.tf32.f32 "
        "{%0,%1,%2,%3}, {%4,%5,%6,%7}, {%8,%9}, {%0,%1,%2,%3};\n"
        : "+f"(c[0]), "+f"(c[1]), "+f"(c[2]), "+f"(c[3])
        : "r"(a[0]), "r"(a[1]), "r"(a[2]), "r"(a[3]), "r"(b0), "r"(b1));
}

// ldmatrix x4: 4 matrices of 8 rows x 16B. For tf32 (b32 elems) this delivers,
// per matrix, element (row=lane>>2, col=lane&3) of an 8x4 b32 quadrant.
__device__ __forceinline__ void ldsm4(uint32_t* r, uint32_t saddr) {
    asm volatile("ldmatrix.sync.aligned.m8n8.x4.shared.b16 {%0,%1,%2,%3}, [%4];"
        : "=r"(r[0]), "=r"(r[1]), "=r"(r[2]), "=r"(r[3]) : "r"(saddr));
}

__device__ __forceinline__ void cp16(uint32_t saddr, const void* gptr) {
    asm volatile("cp.async.cg.shared.global [%0], [%1], 16;" :: "r"(saddr), "l"(gptr));
}

__device__ __forceinline__ uint32_t smem_u32(const void* p) {
    uint32_t a;
    asm("{ .reg .u64 t; cvta.to.shared.u64 t, %1; cvt.u32.u64 %0, t; }" : "=r"(a) : "l"(p));
    return a;
}

// ---------------- weight tf32 pre-round ----------------------------------------------
__global__ void cvt_w_k(const float* __restrict__ src, float* __restrict__ dst, int n4) {
    int stride = gridDim.x * blockDim.x;
    for (int i = blockIdx.x * blockDim.x + threadIdx.x; i < n4; i += stride) {
        float4 v = ((const float4*)src)[i];
        v.x = rtf32(v.x); v.y = rtf32(v.y); v.z = rtf32(v.z); v.w = rtf32(v.w);
        ((float4*)dst)[i] = v;
    }
}

// ---------------- RoPE tables in double precision ------------------------------------
__global__ void rope_tables_k(float* __restrict__ c, float* __restrict__ s) {
    int idx = blockIdx.x * blockDim.x + threadIdx.x;
    int pos = idx >> 5;
    int i   = idx & 31;
    double inv = exp(-((double)(2 * i) / (double)HD) * log(10000.0));
    double ang = (double)pos * inv;
    double cs, sn;
    sincos(ang, &sn, &cs);
    c[idx] = (float)cs;
    s[idx] = (float)sn;
}

// ---------------- RMSNorm (tf32-rounded output) ---------------------------------------
__global__ void rmsnorm_k(const float* __restrict__ x, const float* __restrict__ g,
                          float* __restrict__ o) {
    int row = blockIdx.x;
    const float4* xr = (const float4*)(x + (size_t)row * DIM);
    float4*       orow = (float4*)(o + (size_t)row * DIM);
    int t = threadIdx.x;
    float4 v = xr[t];
    float ss = v.x * v.x + v.y * v.y + v.z * v.z + v.w * v.w;
    #pragma unroll
    for (int off = 16; off; off >>= 1) ss += __shfl_xor_sync(0xffffffffu, ss, off);
    __shared__ float sp[8];
    if ((t & 31) == 0) sp[t >> 5] = ss;
    __syncthreads();
    if (t < 8) {
        float s2 = sp[t];
        #pragma unroll
        for (int off = 4; off; off >>= 1) s2 += __shfl_xor_sync(0xffu, s2, off);
        if (t == 0) sp[0] = s2;
    }
    __syncthreads();
    float rs = rsqrtf(sp[0] * (1.0f / DIM) + 1e-6f);
    float4 gg = ((const float4*)g)[t];
    float4 out;
    out.x = rtf32(v.x * rs * gg.x);
    out.y = rtf32(v.y * rs * gg.y);
    out.z = rtf32(v.z * rs * gg.z);
    out.w = rtf32(v.w * rs * gg.w);
    orow[t] = out;
}

// ---------------- tf32 GEMM: CTA 128x128, warp 64x32, ldmatrix + cp.async -----------
#define BM 128
#define BN 128
#define BK 16
#define SST 20
#define STAGES 3

struct Batch3 {
    const float* B[3];
    float*       C[3];
    const float* R[3];
};

template <bool RESID>
__global__ __launch_bounds__(256, 2)
void gemm_tc(const float* __restrict__ A, Batch3 bt, int M, int N, int K) {
    const float* __restrict__ Bp = bt.B[blockIdx.z];
    float*       __restrict__ Cp = bt.C[blockIdx.z];
    const float* __restrict__ Rp = bt.R[blockIdx.z];

    __shared__ uint32_t As[STAGES][BM][SST];
    __shared__ uint32_t Bs[STAGES][BN][SST];

    const int bm = blockIdx.y * BM;
    const int bn = blockIdx.x * BN;
    const int tid  = threadIdx.x;
    const int warp = tid >> 5;
    const int lane = tid & 31;
    const int grp  = lane >> 2;
    const int tig  = lane & 3;
    const int wm = (warp >> 2) * 64;
    const int wn = (warp & 3) * 32;

    // ldmatrix per-lane row/col offsets
    const int arow = lane & 15;                                // A (and 16-row B blocks)
    const int acol = (lane >> 4) * 4;
    const int brow = ((lane >> 4) << 3) + (lane & 7);
    const int bcol = ((lane >> 3) & 1) * 4;

    const int r0 = tid >> 2;
    const int r1 = r0 + 64;
    const int c4 = (tid & 3) * 4;

    float acc[4][4][4];
    #pragma unroll
    for (int i = 0; i < 4; i++)
        #pragma unroll
        for (int j = 0; j < 4; j++)
            #pragma unroll
            for (int r = 0; r < 4; r++) acc[i][j][r] = 0.0f;

    const int NT = K / BK;

    auto issue = [&](int kt) {
        const int st = kt % STAGES;
        cp16(smem_u32(&As[st][r0][c4]), A  + (size_t)(bm + r0) * K + kt * BK + c4);
        cp16(smem_u32(&As[st][r1][c4]), A  + (size_t)(bm + r1) * K + kt * BK + c4);
        cp16(smem_u32(&Bs[st][r0][c4]), Bp + (size_t)(bn + r0) * K + kt * BK + c4);
        cp16(smem_u32(&Bs[st][r1][c4]), Bp + (size_t)(bn + r1) * K + kt * BK + c4);
        asm volatile("cp.async.commit_group;");
    };

    issue(0);
    issue(1);

    for (int kt = 0; kt < NT; kt++) {
        if (kt + 1 < NT) {
            asm volatile("cp.async.wait_group 1;");
        } else {
            asm volatile("cp.async.wait_group 0;");
        }
        __syncthreads();
        if (kt + 2 < NT) issue(kt + 2);

        const int cur = kt % STAGES;
        const uint32_t ab = smem_u32(&As[cur][0][0]);
        const uint32_t bb = smem_u32(&Bs[cur][0][0]);

        #pragma unroll
        for (int ks = 0; ks < 2; ks++) {
            const int kb = ks * 8;
            uint32_t af[4][4], b2[2][4];
            #pragma unroll
            for (int mt = 0; mt < 4; mt++)
                ldsm4(af[mt], ab + (((wm + mt * 16 + arow) * SST) + kb + acol) * 4);
            ldsm4(b2[0], bb + (((wn +  0 + brow) * SST) + kb + bcol) * 4);
            ldsm4(b2[1], bb + (((wn + 16 + brow) * SST) + kb + bcol) * 4);
            #pragma unroll
            for (int mt = 0; mt < 4; mt++)
                #pragma unroll
                for (int nt = 0; nt < 4; nt++)
                    mma_tf32(acc[mt][nt],
                             af[mt],
                             b2[nt >> 1][(nt & 1) * 2],
                             b2[nt >> 1][(nt & 1) * 2 + 1]);
        }
    }

    #pragma unroll
    for (int mt = 0; mt < 4; mt++) {
        const int row = bm + wm + mt * 16 + grp;
        #pragma unroll
        for (int nt = 0; nt < 4; nt++) {
            const int col = bn + wn + nt * 8 + 2 * tig;
            size_t i0 = (size_t)row * N + col;
            size_t i1 = (size_t)(row + 8) * N + col;
            float2 v0 = make_float2(acc[mt][nt][0], acc[mt][nt][1]);
            float2 v1 = make_float2(acc[mt][nt][2], acc[mt][nt][3]);
            if (RESID) {
                float2 r0v = *(const float2*)&Rp[i0];
                float2 r1v = *(const float2*)&Rp[i1];
                v0.x += r0v.x; v0.y += r0v.y;
                v1.x += r1v.x; v1.y += r1v.y;
            }
            *(float2*)&Cp[i0] = v0;
            *(float2*)&Cp[i1] = v1;
        }
    }
}

// ---------------- RoPE ---------------------------------------------------------------
__global__ void rope_k(float* __restrict__ q, float* __restrict__ k,
                       const float* __restrict__ ct, const float* __restrict__ st) {
    int pos = blockIdx.x;
    int t = threadIdx.x;
    int h = t >> 5;
    int i = t & 31;
    float c = ct[pos * 32 + i];
    float s = st[pos * 32 + i];
    size_t base = (size_t)pos * DIM + h * HD + 2 * i;
    float2 qq = *(float2*)&q[base];
    float2 qo; qo.x = qq.x * c - qq.y * s; qo.y = qq.x * s + qq.y * c;
    *(float2*)&q[base] = qo;
    float2 kk = *(float2*)&k[base];
    float2 ko; ko.x = kk.x * c - kk.y * s; ko.y = kk.x * s + kk.y * c;
    *(float2*)&k[base] = ko;
}

// ---------------- Tensor-core flash attention (tf32, mma.sync + ldmatrix) ------------
#define BQ   64
#define BKV  64
#define KP   68
#define VP   72

__global__ __launch_bounds__(128, 3)
void flash_attn_tc(const float* __restrict__ Q, const float* __restrict__ K,
                   const float* __restrict__ V, float* __restrict__ O) {
    __shared__ uint32_t Ks[BKV][KP];
    __shared__ uint32_t Vs[BKV][VP];
    __shared__ uint32_t Ps[BQ][KP];

    const int h  = blockIdx.y;
    const int q0 = blockIdx.x * BQ;
    const int tid  = threadIdx.x;
    const int warp = tid >> 5;
    const int lane = tid & 31;
    const int grp  = lane >> 2;
    const int tig  = lane & 3;
    const int wm   = warp * 16;

    const int arow = lane & 15;
    const int acol = (lane >> 4) * 4;
    const int brow = ((lane >> 4) << 3) + (lane & 7);
    const int bcol = ((lane >> 3) & 1) * 4;

    uint32_t qf[8][4];
    {
        const float* qb = Q + (size_t)(q0 + wm) * DIM + h * HD;
        #pragma unroll
        for (int ks = 0; ks < 8; ks++) {
            qf[ks][0] = f2tf32(0.125f * qb[(size_t)grp       * DIM + ks * 8 + tig]);
            qf[ks][1] = f2tf32(0.125f * qb[(size_t)(grp + 8) * DIM + ks * 8 + tig]);
            qf[ks][2] = f2tf32(0.125f * qb[(size_t)grp       * DIM + ks * 8 + tig + 4]);
            qf[ks][3] = f2tf32(0.125f * qb[(size_t)(grp + 8) * DIM + ks * 8 + tig + 4]);
        }
    }

    float o[8][4];
    #pragma unroll
    for (int dt = 0; dt < 8; dt++)
        #pragma unroll
        for (int r = 0; r < 4; r++) o[dt][r] = 0.0f;
    float m0 = -1e30f, m1 = -1e30f, l0 = 0.0f, l1 = 0.0f;

    const uint32_t ksb = smem_u32(&Ks[0][0]);
    const uint32_t psb = smem_u32(&Ps[0][0]);

    for (int k0 = 0; k0 < SEQ; k0 += BKV) {
        __syncthreads();
        #pragma unroll
        for (int i = 0; i < 8; i++) {
            int idx = tid + i * 128;
            int row = idx >> 4;
            int c   = (idx & 15) * 4;
            float4 k4 = *(const float4*)&K[(size_t)(k0 + row) * DIM + h * HD + c];
            Ks[row][c + 0] = f2tf32(k4.x); Ks[row][c + 1] = f2tf32(k4.y);
            Ks[row][c + 2] = f2tf32(k4.z); Ks[row][c + 3] = f2tf32(k4.w);
            float4 v4 = *(const float4*)&V[(size_t)(k0 + row) * DIM + h * HD + c];
            Vs[row][c + 0] = f2tf32(v4.x); Vs[row][c + 1] = f2tf32(v4.y);
            Vs[row][c + 2] = f2tf32(v4.z); Vs[row][c + 3] = f2tf32(v4.w);
        }
        __syncthreads();

        float sc[8][4];
        #pragma unroll
        for (int nt = 0; nt < 8; nt++)
            #pragma unroll
            for (int r = 0; r < 4; r++) sc[nt][r] = 0.0f;
        #pragma unroll
        for (int ks = 0; ks < 8; ks++) {
            const int kb = ks * 8;
            uint32_t kf[4][4];
            #pragma unroll
            for (int g = 0; g < 4; g++)
                ldsm4(kf[g], ksb + (((g * 16 + brow) * KP) + kb + bcol) * 4);
            #pragma unroll
            for (int nt = 0; nt < 8; nt++)
                mma_tf32(sc[nt], qf[ks],
                         kf[nt >> 1][(nt & 1) * 2],
                         kf[nt >> 1][(nt & 1) * 2 + 1]);
        }

        float mx0 = -1e30f, mx1 = -1e30f;
        #pragma unroll
        for (int nt = 0; nt < 8; nt++) {
            mx0 = fmaxf(mx0, fmaxf(sc[nt][0], sc[nt][1]));
            mx1 = fmaxf(mx1, fmaxf(sc[nt][2], sc[nt][3]));
        }
        mx0 = fmaxf(mx0, __shfl_xor_sync(0xffffffffu, mx0, 1));
        mx0 = fmaxf(mx0, __shfl_xor_sync(0xffffffffu, mx0, 2));
        mx1 = fmaxf(mx1, __shfl_xor_sync(0xffffffffu, mx1, 1));
        mx1 = fmaxf(mx1, __shfl_xor_sync(0xffffffffu, mx1, 2));

        float mn0 = fmaxf(m0, mx0);
        float mn1 = fmaxf(m1, mx1);
        float cr0 = __expf(m0 - mn0);
        float cr1 = __expf(m1 - mn1);
        m0 = mn0; m1 = mn1;

        float s0 = 0.0f, s1 = 0.0f;
        #pragma unroll
        for (int nt = 0; nt < 8; nt++) {
            sc[nt][0] = __expf(sc[nt][0] - mn0);
            sc[nt][1] = __expf(sc[nt][1] - mn0);
            sc[nt][2] = __expf(sc[nt][2] - mn1);
            sc[nt][3] = __expf(sc[nt][3] - mn1);
            s0 += sc[nt][0] + sc[nt][1];
            s1 += sc[nt][2] + sc[nt][3];
        }
        s0 += __shfl_xor_sync(0xffffffffu, s0, 1);
        s0 += __shfl_xor_sync(0xffffffffu, s0, 2);
        s1 += __shfl_xor_sync(0xffffffffu, s1, 1);
        s1 += __shfl_xor_sync(0xffffffffu, s1, 2);
        l0 = l0 * cr0 + s0;
        l1 = l1 * cr1 + s1;

        #pragma unroll
        for (int dt = 0; dt < 8; dt++) {
            o[dt][0] *= cr0; o[dt][1] *= cr0;
            o[dt][2] *= cr1; o[dt][3] *= cr1;
        }

        #pragma unroll
        for (int nt = 0; nt < 8; nt++) {
            uint2 u0 = make_uint2(f2tf32(sc[nt][0]), f2tf32(sc[nt][1]));
            uint2 u1 = make_uint2(f2tf32(sc[nt][2]), f2tf32(sc[nt][3]));
            *(uint2*)&Ps[wm + grp    ][nt * 8 + 2 * tig] = u0;
            *(uint2*)&Ps[wm + grp + 8][nt * 8 + 2 * tig] = u1;
        }
        __syncwarp();

        #pragma unroll
        for (int ks = 0; ks < 8; ks++) {
            const int kb = ks * 8;
            uint32_t pa[4];
            ldsm4(pa, psb + (((wm + arow) * KP) + kb + acol) * 4);
            #pragma unroll
            for (int dt = 0; dt < 8; dt++) {
                uint32_t b0 = Vs[kb + tig    ][dt * 8 + grp];
                uint32_t b1 = Vs[kb + tig + 4][dt * 8 + grp];
                mma_tf32(o[dt], pa, b0, b1);
            }
        }
        __syncwarp();
    }

    float il0 = 1.0f / l0;
    float il1 = 1.0f / l1;
    #pragma unroll
    for (int dt = 0; dt < 8; dt++) {
        size_t i0 = (size_t)(q0 + wm + grp    ) * DIM + h * HD + dt * 8 + 2 * tig;
        size_t i1 = (size_t)(q0 + wm + grp + 8) * DIM + h * HD + dt * 8 + 2 * tig;
        *(float2*)&O[i0] = make_float2(rtf32(o[dt][0] * il0), rtf32(o[dt][1] * il0));
        *(float2*)&O[i1] = make_float2(rtf32(o[dt][2] * il1), rtf32(o[dt][3] * il1));
    }
}

// ---------------- SwiGLU elementwise (tf32-rounded output) ---------------------------
__global__ void silu_mul_k(float* __restrict__ a, const float* __restrict__ b, int n4) {
    int i = blockIdx.x * blockDim.x + threadIdx.x;
    if (i < n4) {
        float4 x = ((float4*)a)[i];
        float4 y = ((const float4*)b)[i];
        x.x = rtf32(x.x / (1.0f + __expf(-x.x)) * y.x);
        x.y = rtf32(x.y / (1.0f + __expf(-x.y)) * y.y);
        x.z = rtf32(x.z / (1.0f + __expf(-x.z)) * y.z);
        x.w = rtf32(x.w / (1.0f + __expf(-x.w)) * y.w);
        ((float4*)a)[i] = x;
    }
}

// ---------------- launch --------------------------------------------------------------
extern "C" void kernel_launch(void* const* d_in, const int* in_sizes, int n_in,
                              void* d_out, int out_size) {
    const float* x  = (const float*)d_in[0];
    const float* wq = (const float*)d_in[1];
    const float* wk = (const float*)d_in[2];
    const float* wv = (const float*)d_in[3];
    const float* wo = (const float*)d_in[4];
    const float* w1 = (const float*)d_in[5];
    const float* w2 = (const float*)d_in[6];
    const float* w3 = (const float*)d_in[7];
    const float* ga = (const float*)d_in[8];
    const float* gf = (const float*)d_in[9];
    float* out = (float*)d_out;

    float *xn, *q, *k, *v, *at, *hn, *t1, *t3, *ct, *st, *wt;
    cudaGetSymbolAddress((void**)&xn, g_xn);
    cudaGetSymbolAddress((void**)&q,  g_q);
    cudaGetSymbolAddress((void**)&k,  g_k);
    cudaGetSymbolAddress((void**)&v,  g_v);
    cudaGetSymbolAddress((void**)&at, g_at);
    cudaGetSymbolAddress((void**)&hn, g_hn);
    cudaGetSymbolAddress((void**)&t1, g_t1);
    cudaGetSymbolAddress((void**)&t3, g_t3);
    cudaGetSymbolAddress((void**)&ct, g_cos);
    cudaGetSymbolAddress((void**)&st, g_sin);
    cudaGetSymbolAddress((void**)&wt, g_wt);

    cvt_w_k<<<256, 256>>>(wq, wt + WQO, DIM * DIM / 4);
    cvt_w_k<<<256, 256>>>(wk, wt + WKO, DIM * DIM / 4);
    cvt_w_k<<<256, 256>>>(wv, wt + WVO, DIM * DIM / 4);
    cvt_w_k<<<256, 256>>>(wo, wt + WOO, DIM * DIM / 4);
    cvt_w_k<<<512, 256>>>(w1, wt + W1O, HIDDEN * DIM / 4);
    cvt_w_k<<<512, 256>>>(w3, wt + W3O, HIDDEN * DIM / 4);
    cvt_w_k<<<512, 256>>>(w2, wt + W2O, DIM * HIDDEN / 4);

    rope_tables_k<<<(SEQ * 32) / 256, 256>>>(ct, st);
    rmsnorm_k<<<SEQ, 256>>>(x, ga, xn);

    // QKV batched (z = 3)
    {
        Batch3 bt;
        bt.B[0] = wt + WQO; bt.B[1] = wt + WKO; bt.B[2] = wt + WVO;
        bt.C[0] = q; bt.C[1] = k; bt.C[2] = v;
        bt.R[0] = bt.R[1] = bt.R[2] = nullptr;
        gemm_tc<false><<<dim3(DIM / BN, SEQ / BM, 3), 256>>>(xn, bt, SEQ, DIM, DIM);
    }

    rope_k<<<SEQ, 512>>>(q, k, ct, st);
    flash_attn_tc<<<dim3(SEQ / BQ, NH), 128>>>(q, k, v, at);

    // Wo + residual -> out
    {
        Batch3 bt;
        bt.B[0] = wt + WOO; bt.C[0] = out; bt.R[0] = x;
        bt.B[1] = bt.B[2] = nullptr; bt.C[1] = bt.C[2] = nullptr; bt.R[1] = bt.R[2] = nullptr;
        gemm_tc<true><<<dim3(DIM / BN, SEQ / BM, 1), 256>>>(at, bt, SEQ, DIM, DIM);
    }

    rmsnorm_k<<<SEQ, 256>>>(out, gf, hn);

    // w1 / w3 batched (z = 2)
    {
        Batch3 bt;
        bt.B[0] = wt + W1O; bt.B[1] = wt + W3O; bt.B[2] = nullptr;
        bt.C[0] = t1; bt.C[1] = t3; bt.C[2] = nullptr;
        bt.R[0] = bt.R[1] = bt.R[2] = nullptr;
        gemm_tc<false><<<dim3(HIDDEN / BN, SEQ / BM, 2), 256>>>(hn, bt, SEQ, HIDDEN, DIM);
    }

    silu_mul_k<<<(SEQ * HIDDEN / 4 + 255) / 256, 256>>>(t1, t3, SEQ * HIDDEN / 4);

    // W2 + residual -> out
    {
        Batch3 bt;
        bt.B[0] = wt + W2O; bt.C[0] = out; bt.R[0] = out;
        bt.B[1] = bt.B[2] = nullptr; bt.C[1] = bt.C[2] = nullptr; bt.R[1] = bt.R[2] = nullptr;
        gemm_tc<true><<<dim3(DIM / BN, SEQ / BM, 1), 256>>>(t1, bt, SEQ, DIM, HIDDEN);
    }
}